// round 15
// baseline (speedup 1.0000x reference)
#include <cuda_runtime.h>
#include <cuda_fp16.h>

// RelTemporalEncoding collapsed (exact by linearity):
//   Y = emb @ W^T + b            (3000x62 one-time precompute, fp32 math)
//   out[n,:] = w0*Y[t0] + w1*Y[t1] + w2*Y[t2]
//
// R15: THREE pre-scaled fp16 tables (A=w0*Y, C=w1*Y, S=w2*Y) turn the
// gather into a pure 3-way add: cs = HADD2(c,s) in fp16 (c+s is only 1.7%
// of the output -> its rounding is ~8e-6 relative), out = f32(a)+f32(cs).
// Cuts hot-loop instrs ~42 -> ~30 per pair, attacking the issue=61.4%
// co-bound seen in R14. Memory side unchanged from R14 (wavefront floor):
//  - t: one LDG (6 contiguous ints/pair) + SHFL broadcast
//  - Y: 3 gathers/row, 1 dense 128B line each
//  - stores: shfl-realigned full-density STG.128 (496B pair region)
//
// Inputs: t int32 [1e6,3], emb f32 [3000,62], W f32 [62,62], b f32 [62]
// Output: f32 [1e6, 62]

#define N_HID   62
#define MAX_LEN 3000
#define YP      64              // half-pitch: 64 halves = 128B per table row
#define GT      256
#define GBLKS   (148 * 8)
#define FULLM   0xFFFFFFFFu

#define W0 (3600.0f / 3661.0f)
#define W1 (60.0f   / 3661.0f)
#define W2 (1.0f    / 3661.0f)

// Pre-scaled fp16 tables (device global scratch; allocation forbidden)
__device__ __half g_A[MAX_LEN * YP];   // w0 * Y
__device__ __half g_C[MAX_LEN * YP];   // w1 * Y
__device__ __half g_S[MAX_LEN * YP];   // w2 * Y

// ---------------------------------------------------------------------------
// Kernel 1: Y = emb @ W^T + b -> three pre-scaled fp16 tables.
// ---------------------------------------------------------------------------
#define PR 4
__global__ void precompute_Y(const float* __restrict__ emb,
                             const float* __restrict__ W,
                             const float* __restrict__ b) {
    __shared__ float se[PR][N_HID];
    const int r0 = blockIdx.x * PR;
    const int o  = threadIdx.x;          // 0..63

    for (int i = o; i < PR * N_HID; i += 64)
        se[i / N_HID][i % N_HID] = emb[r0 * N_HID + i];
    __syncthreads();

    float acc[PR] = {0.f, 0.f, 0.f, 0.f};
    if (o < N_HID) {
        const float* wrow = W + o * N_HID;
        const float bb = b[o];
        #pragma unroll
        for (int r = 0; r < PR; ++r) acc[r] = bb;
        #pragma unroll
        for (int d = 0; d < N_HID; ++d) {
            const float w = __ldg(&wrow[d]);
            #pragma unroll
            for (int r = 0; r < PR; ++r)
                acc[r] = fmaf(se[r][d], w, acc[r]);
        }
    } else {
        // keep padding zero
    }
    #pragma unroll
    for (int r = 0; r < PR; ++r) {
        const float y = (o < N_HID) ? acc[r] : 0.0f;
        g_A[(r0 + r) * YP + o] = __float2half_rn(y * W0);
        g_C[(r0 + r) * YP + o] = __float2half_rn(y * W1);
        g_S[(r0 + r) * YP + o] = __float2half_rn(y * W2);
    }
}

// ---------------------------------------------------------------------------
// Per-pair compute: 3-way add of pre-scaled halves.
// Lane's float4 = row's cols 4c..4c+3 (c==15: .z/.w garbage, never stored).
// ---------------------------------------------------------------------------
__device__ __forceinline__ float4 sum4(float2 av, float2 cv, float2 sv) {
    const __half2* ah = (const __half2*)&av;
    const __half2* ch = (const __half2*)&cv;
    const __half2* sh = (const __half2*)&sv;

    const __half2 cs0 = __hadd2(ch[0], sh[0]);   // tiny terms: fp16-safe
    const __half2 cs1 = __hadd2(ch[1], sh[1]);

    const float2 a0 = __half22float2(ah[0]), a1 = __half22float2(ah[1]);
    const float2 g0 = __half22float2(cs0),   g1 = __half22float2(cs1);

    float4 r;
    r.x = a0.x + g0.x;
    r.y = a0.y + g0.y;
    r.z = a1.x + g1.x;
    r.w = a1.y + g1.y;
    return r;
}

// Shuffle-realign + store one pair's 496B region as 31 aligned float4s.
__device__ __forceinline__ void store_pair(float4 r, float4* __restrict__ out4,
                                           long long p, int lane) {
    const float nx = __shfl_down_sync(FULLM, r.x, 1);
    const float ny = __shfl_down_sync(FULLM, r.y, 1);

    float4 s;
    if (lane < 15)       s = r;                              // rowA cols 4l..4l+3
    else if (lane == 15) s = make_float4(r.x, r.y, nx, ny);  // A:60,61 | B:0,1
    else                 s = make_float4(r.z, r.w, nx, ny);  // B: 4c+2..4c+5
    if (lane < 31)
        __stcs(&out4[p * 31 + lane], s);
}

// ---------------------------------------------------------------------------
// Kernel 2: persistent warp-per-row-pair gather, 2 pairs in flight.
// ---------------------------------------------------------------------------
__global__ __launch_bounds__(GT)
void gather_pair(const int* __restrict__ t, float4* __restrict__ out4,
                 int n_pairs) {
    const int lane   = threadIdx.x & 31;
    const int warp_g = (blockIdx.x * GT + threadIdx.x) >> 5;
    const int nwarps = (GBLKS * GT) >> 5;          // 9472

    const int tb = (lane >= 16) ? 3 : 0;           // triplet base within pair
    const int c  = lane & 15;                      // column group

    const float2* __restrict__ A2 = (const float2*)g_A;
    const float2* __restrict__ C2 = (const float2*)g_C;
    const float2* __restrict__ S2 = (const float2*)g_S;

    int p = warp_g;
    for (; p + nwarps < n_pairs; p += 2 * nwarps) {
        const int p1 = p + nwarps;

        // Phase 1: t loads (lanes 0..5 load the pair's 6 contiguous ints)
        int tv0 = 0, tv1 = 0;
        if (lane < 6) {
            tv0 = __ldg(&t[6 * p  + lane]);
            tv1 = __ldg(&t[6 * p1 + lane]);
        }
        const int a0 = __shfl_sync(FULLM, tv0, tb + 0);
        const int a1 = __shfl_sync(FULLM, tv0, tb + 1);
        const int a2 = __shfl_sync(FULLM, tv0, tb + 2);
        const int b0 = __shfl_sync(FULLM, tv1, tb + 0);
        const int b1 = __shfl_sync(FULLM, tv1, tb + 1);
        const int b2 = __shfl_sync(FULLM, tv1, tb + 2);

        // Phase 2: all gathers in flight (6 LDG.64 per lane)
        const float2 av0 = __ldg(&A2[a0 * 16 + c]);
        const float2 cv0 = __ldg(&C2[a1 * 16 + c]);
        const float2 sv0 = __ldg(&S2[a2 * 16 + c]);
        const float2 av1 = __ldg(&A2[b0 * 16 + c]);
        const float2 cv1 = __ldg(&C2[b1 * 16 + c]);
        const float2 sv1 = __ldg(&S2[b2 * 16 + c]);

        // Phase 3: 3-way add + shuffled aligned stores
        store_pair(sum4(av0, cv0, sv0), out4, p,  lane);
        store_pair(sum4(av1, cv1, sv1), out4, p1, lane);
    }
    for (; p < n_pairs; p += nwarps) {
        int tv = 0;
        if (lane < 6) tv = __ldg(&t[6 * p + lane]);
        const int q0 = __shfl_sync(FULLM, tv, tb + 0);
        const int q1 = __shfl_sync(FULLM, tv, tb + 1);
        const int q2 = __shfl_sync(FULLM, tv, tb + 2);
        store_pair(sum4(__ldg(&A2[q0 * 16 + c]),
                        __ldg(&C2[q1 * 16 + c]),
                        __ldg(&S2[q2 * 16 + c])), out4, p, lane);
    }
}

// Fallback for an odd final row (not hit for n_rows = 1e6; kept for safety).
__global__ void gather_last_row(const int* __restrict__ t,
                                float* __restrict__ out, int row) {
    const int c = threadIdx.x;                  // 0..15
    const int t0 = t[row * 3 + 0], t1 = t[row * 3 + 1], t2 = t[row * 3 + 2];
    const float2* A2 = (const float2*)g_A;
    const float2* C2 = (const float2*)g_C;
    const float2* S2 = (const float2*)g_S;
    float4 r = sum4(__ldg(&A2[t0 * 16 + c]),
                    __ldg(&C2[t1 * 16 + c]),
                    __ldg(&S2[t2 * 16 + c]));
    float* o = out + (size_t)row * N_HID + c * 4;
    o[0] = r.x; o[1] = r.y;
    if (c < 15) { o[2] = r.z; o[3] = r.w; }
}

// ---------------------------------------------------------------------------
extern "C" void kernel_launch(void* const* d_in, const int* in_sizes, int n_in,
                              void* d_out, int out_size) {
    const int*   t   = (const int*)  d_in[0];
    const float* emb = (const float*)d_in[1];
    const float* W   = (const float*)d_in[2];
    const float* b   = (const float*)d_in[3];

    precompute_Y<<<MAX_LEN / PR, 64>>>(emb, W, b);    // 750 blocks

    const int n_rows  = out_size / N_HID;             // 1,000,000
    const int n_pairs = n_rows / 2;                   // 500,000
    gather_pair<<<GBLKS, GT>>>(t, (float4*)d_out, n_pairs);
    if (n_rows & 1)
        gather_last_row<<<1, 16>>>(t, (float*)d_out, n_rows - 1);
}